// round 9
// baseline (speedup 1.0000x reference)
#include <cuda_runtime.h>
#include <math.h>
#include <cstdint>

#define NN 50000
#define NE 800000
#define CH 64
#define SEQL 8
#define KB 192

static const size_t SL  = (size_t)NN * CH;   // per-timestep state slice
static const size_t SLK = (size_t)NN * KB;   // per-timestep basis slice

// ---------------- static scratch ----------------
__device__ float g_deg[NN];
__device__ float g_dinv[NN];
__device__ int   g_cnt[NN];
__device__ int   g_off[NN + 1];
__device__ int   g_cur[NN];
__device__ int2  g_cw[NE];                       // packed {col, w-bits}
__device__ float g_XBX[(size_t)SEQL * NN * KB];  // X basis, all timesteps
__device__ float g_XBH[(size_t)NN * KB];         // H/HR basis (reused per t)
__device__ float g_GX [(size_t)SEQL * NN * KB];  // x-gate preactivations, all t
__device__ float g_Z  [(size_t)NN * CH];
__device__ float g_HR [(size_t)NN * CH];
__device__ float g_BX [192 * KB];                // transposed tf32-rounded weights
__device__ float g_BZR[128 * KB];
__device__ float g_BH [64 * KB];
__device__ float g_bX [192];
__device__ float g_bZR[128];

// ---------------- tf32 helpers ----------------
__device__ __forceinline__ float tf32r(float f) {
    uint32_t u;
    asm("cvt.rna.tf32.f32 %0, %1;" : "=r"(u) : "f"(f));
    return __uint_as_float(u);
}
__device__ __forceinline__ float4 tf32r4(float4 v) {
    return make_float4(tf32r(v.x), tf32r(v.y), tf32r(v.z), tf32r(v.w));
}
__device__ __forceinline__ void mma_tf32(float* d, const uint32_t* a, const uint32_t* b) {
    asm volatile(
        "mma.sync.aligned.m16n8k8.row.col.f32.tf32.tf32.f32 "
        "{%0,%1,%2,%3}, {%4,%5,%6,%7}, {%8,%9}, {%0,%1,%2,%3};\n"
        : "+f"(d[0]), "+f"(d[1]), "+f"(d[2]), "+f"(d[3])
        : "r"(a[0]), "r"(a[1]), "r"(a[2]), "r"(a[3]), "r"(b[0]), "r"(b[1]));
}

// ---------------- setup kernels ----------------
__global__ void k_zero_setup() {
    int i = blockIdx.x * blockDim.x + threadIdx.x;
    if (i < NN) { g_deg[i] = 0.f; g_cnt[i] = 0; g_cur[i] = 0; }
}
__global__ void k_edgepre(const int* __restrict__ ei, const float* __restrict__ ew) {
    int e = blockIdx.x * blockDim.x + threadIdx.x;
    if (e < NE) {
        int r = ei[e], c = ei[NE + e];
        if (r != c) atomicAdd(&g_deg[r], ew[e]);
        atomicAdd(&g_cnt[r], 1);
    }
}
__global__ void k_dinv() {
    int i = blockIdx.x * blockDim.x + threadIdx.x;
    if (i < NN) {
        float d = g_deg[i];
        g_dinv[i] = d > 0.f ? rsqrtf(d) : 0.f;
    }
}
__global__ void k_scan() {
    __shared__ int sh[1024];
    int tid = threadIdx.x;
    const int chunk = (NN + 1023) / 1024;
    int base = tid * chunk, s = 0;
    for (int i = 0; i < chunk; i++) { int idx = base + i; if (idx < NN) s += g_cnt[idx]; }
    sh[tid] = s;
    __syncthreads();
    for (int d = 1; d < 1024; d <<= 1) {
        int v = (tid >= d) ? sh[tid - d] : 0;
        __syncthreads(); sh[tid] += v; __syncthreads();
    }
    int run = (tid == 0) ? 0 : sh[tid - 1];
    for (int i = 0; i < chunk; i++) {
        int idx = base + i;
        if (idx < NN) { g_off[idx] = run; run += g_cnt[idx]; }
    }
    if (tid == 0) g_off[NN] = sh[1023];
}
__global__ void k_scatter(const int* __restrict__ ei, const float* __restrict__ ew) {
    int e = blockIdx.x * blockDim.x + threadIdx.x;
    if (e < NE) {
        int r = ei[e], c = ei[NE + e];
        float w = (r == c) ? 0.f : ew[e];
        float wn = -w * g_dinv[r] * g_dinv[c];
        int pos = g_off[r] + atomicAdd(&g_cur[r], 1);
        g_cw[pos] = make_int2(c, __float_as_int(wn));
    }
}
// build transposed weight matrices B[n_out][k], tf32-rounded; concat biases
__global__ void k_prepB(const float* __restrict__ Wxz, const float* __restrict__ Wxr,
                        const float* __restrict__ Wxh, const float* __restrict__ Whz,
                        const float* __restrict__ Whr, const float* __restrict__ Whh,
                        const float* __restrict__ bxz, const float* __restrict__ bxr,
                        const float* __restrict__ bxh, const float* __restrict__ bhz,
                        const float* __restrict__ bhr) {
    int i = blockIdx.x * blockDim.x + threadIdx.x;
    if (i < 192 * KB) {
        int n = i / KB, k = i % KB, kc = k / 64, ci = k & 63, gate = n / 64, c = n & 63;
        const float* W = gate == 0 ? Wxz : (gate == 1 ? Wxr : Wxh);
        g_BX[i] = tf32r(W[kc * 4096 + ci * 64 + c]);
    }
    if (i < 128 * KB) {
        int n = i / KB, k = i % KB, kc = k / 64, ci = k & 63, c = n & 63;
        const float* W = n < 64 ? Whz : Whr;
        g_BZR[i] = tf32r(W[kc * 4096 + ci * 64 + c]);
    }
    if (i < 64 * KB) {
        int n = i / KB, k = i % KB, kc = k / 64, ci = k & 63;
        g_BH[i] = tf32r(Whh[kc * 4096 + ci * 64 + (n & 63)]);
    }
    if (i < 192) g_bX[i] = i < 64 ? bxz[i] : (i < 128 ? bxr[i - 64] : bxh[i - 128]);
    if (i < 128) g_bZR[i] = i < 64 ? bhz[i] : bhr[i - 64];
}

// ---------------- SpMM (half-warp per edge, float4 channels) ----------------
// spmmA: XB[:,0:64] = round(v); XB[:,64:128] = round(S @ v)
__global__ void k_spmmA(const float* __restrict__ vin, float* __restrict__ XB) {
    int warp = (blockIdx.x * blockDim.x + threadIdx.x) >> 5;
    if (warp >= NN) return;
    int lane = threadIdx.x & 31, eh = lane >> 4, cg = lane & 15;
    const float4* v4 = (const float4*)(vin + (size_t)blockIdx.y * SL);
    float* xb = XB + (size_t)blockIdx.y * SLK;
    int s = g_off[warp], e = g_off[warp + 1];
    float4 a0 = make_float4(0.f, 0.f, 0.f, 0.f);
    float4 a1 = make_float4(0.f, 0.f, 0.f, 0.f);
    int j = s + eh;
    for (; j + 2 < e; j += 4) {
        int2 cw0 = g_cw[j], cw1 = g_cw[j + 2];
        float w0 = __int_as_float(cw0.y), w1 = __int_as_float(cw1.y);
        float4 u0 = v4[(size_t)cw0.x * 16 + cg];
        float4 u1 = v4[(size_t)cw1.x * 16 + cg];
        a0.x += w0 * u0.x; a0.y += w0 * u0.y; a0.z += w0 * u0.z; a0.w += w0 * u0.w;
        a1.x += w1 * u1.x; a1.y += w1 * u1.y; a1.z += w1 * u1.z; a1.w += w1 * u1.w;
    }
    if (j < e) {
        int2 cw = g_cw[j];
        float w = __int_as_float(cw.y);
        float4 u = v4[(size_t)cw.x * 16 + cg];
        a0.x += w * u.x; a0.y += w * u.y; a0.z += w * u.z; a0.w += w * u.w;
    }
    a0.x += a1.x; a0.y += a1.y; a0.z += a1.z; a0.w += a1.w;
    a0.x += __shfl_xor_sync(0xffffffffu, a0.x, 16);
    a0.y += __shfl_xor_sync(0xffffffffu, a0.y, 16);
    a0.z += __shfl_xor_sync(0xffffffffu, a0.z, 16);
    a0.w += __shfl_xor_sync(0xffffffffu, a0.w, 16);
    if (eh == 0) {
        float4 t0 = v4[(size_t)warp * 16 + cg];
        float* o = xb + (size_t)warp * KB;
        ((float4*)o)[cg]        = tf32r4(t0);
        ((float4*)(o + 64))[cg] = tf32r4(a0);
    }
}
// spmmB: XB[:,128:192] = round(2 * (S @ T1) - T0)
__global__ void k_spmmB(float* __restrict__ XB) {
    int warp = (blockIdx.x * blockDim.x + threadIdx.x) >> 5;
    if (warp >= NN) return;
    int lane = threadIdx.x & 31, eh = lane >> 4, cg = lane & 15;
    float* xb = XB + (size_t)blockIdx.y * SLK;
    const float4* x4 = (const float4*)xb;
    int s = g_off[warp], e = g_off[warp + 1];
    float4 a0 = make_float4(0.f, 0.f, 0.f, 0.f);
    float4 a1 = make_float4(0.f, 0.f, 0.f, 0.f);
    int j = s + eh;
    for (; j + 2 < e; j += 4) {
        int2 cw0 = g_cw[j], cw1 = g_cw[j + 2];
        float w0 = __int_as_float(cw0.y), w1 = __int_as_float(cw1.y);
        float4 u0 = x4[(size_t)cw0.x * 48 + 16 + cg];
        float4 u1 = x4[(size_t)cw1.x * 48 + 16 + cg];
        a0.x += w0 * u0.x; a0.y += w0 * u0.y; a0.z += w0 * u0.z; a0.w += w0 * u0.w;
        a1.x += w1 * u1.x; a1.y += w1 * u1.y; a1.z += w1 * u1.z; a1.w += w1 * u1.w;
    }
    if (j < e) {
        int2 cw = g_cw[j];
        float w = __int_as_float(cw.y);
        float4 u = x4[(size_t)cw.x * 48 + 16 + cg];
        a0.x += w * u.x; a0.y += w * u.y; a0.z += w * u.z; a0.w += w * u.w;
    }
    a0.x += a1.x; a0.y += a1.y; a0.z += a1.z; a0.w += a1.w;
    a0.x += __shfl_xor_sync(0xffffffffu, a0.x, 16);
    a0.y += __shfl_xor_sync(0xffffffffu, a0.y, 16);
    a0.z += __shfl_xor_sync(0xffffffffu, a0.z, 16);
    a0.w += __shfl_xor_sync(0xffffffffu, a0.w, 16);
    if (eh == 0) {
        float* o = xb + (size_t)warp * KB;
        float4 t0 = ((const float4*)o)[cg];
        float4 r;
        r.x = tf32r(2.f * a0.x - t0.x);
        r.y = tf32r(2.f * a0.y - t0.y);
        r.z = tf32r(2.f * a0.z - t0.z);
        r.w = tf32r(2.f * a0.w - t0.w);
        ((float4*)(o + 128))[cg] = r;
    }
}

// ---------------- tf32 mma.sync GEMM, fused epilogues ----------------
// D[128 x NOUT] = A[128 x 192] @ B[NOUT x 192]^T (inputs pre-rounded to tf32)
// EPI 0: out[r*192+c] = acc + bias                                   (GX)
// EPI 1: c<64: Z = sigmoid(acc+bias+GX[r,c]); c>=64: HR = H[r,c-64]*sigmoid(...)
// EPI 2: Ht = tanh(acc+bias+GX[r,128+c]); out = Z*H + (1-Z)*Ht       (States)
#define PADK 36

template <int NOUT, int EPI>
__global__ void __launch_bounds__(128 * (NOUT / 64)) k_mgemm(
    const float* __restrict__ A, const float* __restrict__ B,
    const float* __restrict__ bias, const float* __restrict__ GX,
    const float* __restrict__ H, const float* __restrict__ Z,
    float* __restrict__ out, float* __restrict__ out2, int rows,
    size_t ayStride, size_t oyStride)
{
    __shared__ uint32_t As[128 * PADK];
    __shared__ uint32_t Bs[NOUT * PADK];

    A   += (size_t)blockIdx.y * ayStride;
    out += (size_t)blockIdx.y * oyStride;

    const int NTH = 128 * (NOUT / 64);
    int tid = threadIdx.x;
    int wid = tid >> 5, lane = tid & 31;
    int mw = wid & 3;          // M warp group: rows mw*32..+31
    int nw = wid >> 2;         // N warp group: cols nw*64..+63
    int rb = blockIdx.x * 128;

    float acc[2][8][4];
#pragma unroll
    for (int mt = 0; mt < 2; mt++)
#pragma unroll
        for (int nt = 0; nt < 8; nt++)
#pragma unroll
            for (int q = 0; q < 4; q++) acc[mt][nt][q] = 0.f;

    for (int kc = 0; kc < 6; kc++) {
        // stage A tile: 128 rows x 32 k (raw bit copies, data pre-rounded)
#pragma unroll
        for (int idx = tid; idx < 1024; idx += NTH) {
            int row = idx >> 3, q = idx & 7;
            uint4 v = make_uint4(0u, 0u, 0u, 0u);
            int gr = rb + row;
            if (gr < rows) v = *(const uint4*)(A + (size_t)gr * KB + kc * 32 + q * 4);
            uint32_t* p = &As[row * PADK + q * 4];
            p[0] = v.x; p[1] = v.y; p[2] = v.z; p[3] = v.w;
        }
        // stage B tile: NOUT rows x 32 k
#pragma unroll
        for (int idx = tid; idx < NOUT * 8; idx += NTH) {
            int row = idx >> 3, q = idx & 7;
            uint4 v = *(const uint4*)(B + (size_t)row * KB + kc * 32 + q * 4);
            uint32_t* p = &Bs[row * PADK + q * 4];
            p[0] = v.x; p[1] = v.y; p[2] = v.z; p[3] = v.w;
        }
        __syncthreads();
#pragma unroll
        for (int kk = 0; kk < 4; kk++) {
            uint32_t a[2][4];
#pragma unroll
            for (int mt = 0; mt < 2; mt++) {
                int r = mw * 32 + mt * 16 + (lane >> 2);
                int c = kk * 8 + (lane & 3);
                a[mt][0] = As[r * PADK + c];
                a[mt][1] = As[(r + 8) * PADK + c];
                a[mt][2] = As[r * PADK + c + 4];
                a[mt][3] = As[(r + 8) * PADK + c + 4];
            }
            uint32_t b[8][2];
#pragma unroll
            for (int nt = 0; nt < 8; nt++) {
                int n = nw * 64 + nt * 8 + (lane >> 2);
                int c = kk * 8 + (lane & 3);
                b[nt][0] = Bs[n * PADK + c];
                b[nt][1] = Bs[n * PADK + c + 4];
            }
#pragma unroll
            for (int mt = 0; mt < 2; mt++)
#pragma unroll
                for (int nt = 0; nt < 8; nt++)
                    mma_tf32(acc[mt][nt], a[mt], b[nt]);
        }
        __syncthreads();
    }

    // epilogue: each thread owns float2 at (r, c) and (r+8, c) per tile
#pragma unroll
    for (int mt = 0; mt < 2; mt++) {
#pragma unroll
        for (int nt = 0; nt < 8; nt++) {
            int c = nw * 64 + nt * 8 + (lane & 3) * 2;
            float bx = bias[c], by = bias[c + 1];
#pragma unroll
            for (int hh = 0; hh < 2; hh++) {
                int r = rb + mw * 32 + mt * 16 + (lane >> 2) + hh * 8;
                if (r >= rows) continue;
                float vx = acc[mt][nt][hh * 2] + bx;
                float vy = acc[mt][nt][hh * 2 + 1] + by;
                if (EPI == 0) {
                    *(float2*)(out + (size_t)r * KB + c) = make_float2(vx, vy);
                } else if (EPI == 1) {
                    float2 gx = *(const float2*)(GX + (size_t)r * KB + c);
                    float sx = 1.f / (1.f + expf(-(vx + gx.x)));
                    float sy = 1.f / (1.f + expf(-(vy + gx.y)));
                    if (c < 64) {
                        *(float2*)(out + (size_t)r * CH + c) = make_float2(sx, sy);
                    } else {
                        float2 h = *(const float2*)(H + (size_t)r * CH + (c - 64));
                        *(float2*)(out2 + (size_t)r * CH + (c - 64)) =
                            make_float2(h.x * sx, h.y * sy);
                    }
                } else {
                    float2 gx = *(const float2*)(GX + (size_t)r * KB + 128 + c);
                    float2 h  = *(const float2*)(H + (size_t)r * CH + c);
                    float2 z2 = *(const float2*)(Z + (size_t)r * CH + c);
                    float tx = tanhf(vx + gx.x), ty = tanhf(vy + gx.y);
                    *(float2*)(out + (size_t)r * CH + c) = make_float2(
                        z2.x * h.x + (1.f - z2.x) * tx,
                        z2.y * h.y + (1.f - z2.y) * ty);
                }
            }
        }
    }
}

// t = 0 shortcut: H0 = 0 => HR = 0 => Hn = (1 - sigmoid(GXz + b_hz)) * tanh(GXh + b_hh)
__global__ void k_t0(const float* __restrict__ GX, const float* __restrict__ bhz,
                     const float* __restrict__ bhh, float* __restrict__ out) {
    int i = blockIdx.x * blockDim.x + threadIdx.x;
    if (i >= NN * CH) return;
    int r = i >> 6, c = i & 63;
    float z  = 1.f / (1.f + expf(-(GX[(size_t)r * KB + c] + bhz[c])));
    float ht = tanhf(GX[(size_t)r * KB + 128 + c] + bhh[c]);
    out[i] = (1.f - z) * ht;
}

__global__ void k_copy(const float* __restrict__ src, float* __restrict__ dst, int n) {
    int i = blockIdx.x * blockDim.x + threadIdx.x;
    if (i < n) dst[i] = src[i];
}

// ---------------- host side ----------------
extern "C" void kernel_launch(void* const* d_in, const int* in_sizes, int n_in,
                              void* d_out, int out_size) {
    const float* X    = (const float*)d_in[0];
    const int*   ei   = (const int*)  d_in[1];
    const float* ew   = (const float*)d_in[2];
    const float* W_xz = (const float*)d_in[3];
    const float* b_xz = (const float*)d_in[4];
    const float* W_hz = (const float*)d_in[5];
    const float* b_hz = (const float*)d_in[6];
    const float* W_xr = (const float*)d_in[7];
    const float* b_xr = (const float*)d_in[8];
    const float* W_hr = (const float*)d_in[9];
    const float* b_hr = (const float*)d_in[10];
    const float* W_xh = (const float*)d_in[11];
    const float* b_xh = (const float*)d_in[12];
    const float* W_hh = (const float*)d_in[13];
    const float* b_hh = (const float*)d_in[14];
    float* out = (float*)d_out;

    float *pXBX, *pXBH, *pGX, *pZ, *pHR, *pBX, *pBZR, *pBH, *pbX, *pbZR;
    cudaGetSymbolAddress((void**)&pXBX, g_XBX);
    cudaGetSymbolAddress((void**)&pXBH, g_XBH);
    cudaGetSymbolAddress((void**)&pGX,  g_GX);
    cudaGetSymbolAddress((void**)&pZ,   g_Z);
    cudaGetSymbolAddress((void**)&pHR,  g_HR);
    cudaGetSymbolAddress((void**)&pBX,  g_BX);
    cudaGetSymbolAddress((void**)&pBZR, g_BZR);
    cudaGetSymbolAddress((void**)&pBH,  g_BH);
    cudaGetSymbolAddress((void**)&pbX,  g_bX);
    cudaGetSymbolAddress((void**)&pbZR, g_bZR);

    const int NB_NODE = (NN + 255) / 256;
    const int NB_EDGE = (NE + 255) / 256;
    const int NB_SPMM = (NN * 32 + 255) / 256;
    const int NB_GEMM = (NN + 127) / 128;

    // graph normalization + CSR + weight prep
    k_zero_setup<<<NB_NODE, 256>>>();
    k_edgepre<<<NB_EDGE, 256>>>(ei, ew);
    k_dinv<<<NB_NODE, 256>>>();
    k_scan<<<1, 1024>>>();
    k_scatter<<<NB_EDGE, 256>>>(ei, ew);
    k_prepB<<<(192 * KB + 255) / 256, 256>>>(W_xz, W_xr, W_xh, W_hz, W_hr, W_hh,
                                             b_xz, b_xr, b_xh, b_hz, b_hr);

    // X-stage for ALL timesteps (X is a pure input): 3 batched launches
    {
        dim3 gs(NB_SPMM, SEQL), gg(NB_GEMM, SEQL);
        k_spmmA<<<gs, 256>>>(X, pXBX);
        k_spmmB<<<gs, 256>>>(pXBX);
        k_mgemm<192, 0><<<gg, 384>>>(pXBX, pBX, pbX, nullptr, nullptr, nullptr,
                                     pGX, nullptr, NN, SLK, SLK);
    }

    // t = 0 shortcut (H0 = 0)
    k_t0<<<(NN * CH + 255) / 256, 256>>>(pGX, b_hz, b_hh, out);

    // t = 1..7 recurrent chain
    for (int t = 1; t < SEQL; t++) {
        const float* Hp  = out + (size_t)(t - 1) * SL;
        const float* GXt = pGX + (size_t)t * SLK;
        float* Ot = out + (size_t)t * SL;

        k_spmmA<<<NB_SPMM, 256>>>(Hp, pXBH);
        k_spmmB<<<NB_SPMM, 256>>>(pXBH);
        k_mgemm<128, 1><<<NB_GEMM, 256>>>(pXBH, pBZR, pbZR, GXt, Hp, nullptr,
                                          pZ, pHR, NN, 0, 0);
        k_spmmA<<<NB_SPMM, 256>>>(pHR, pXBH);
        k_spmmB<<<NB_SPMM, 256>>>(pXBH);
        k_mgemm<64, 2><<<NB_GEMM, 128>>>(pXBH, pBH, b_hh, GXt, Hp, pZ,
                                         Ot, nullptr, NN, 0, 0);
    }

    // Hlast = States[:, -1]
    if (out_size >= (int)((SEQL + 1) * SL)) {
        int n = (int)SL;
        k_copy<<<(n + 255) / 256, 256>>>(out + (size_t)(SEQL - 1) * SL,
                                         out + (size_t)SEQL * SL, n);
    }
}

// round 11
// speedup vs baseline: 1.2635x; 1.2635x over previous
#include <cuda_runtime.h>
#include <cuda_fp16.h>
#include <math.h>
#include <cstdint>

#define NN 50000
#define NE 800000
#define CH 64
#define SEQL 8
#define KB 192
#define SCB 49   // scan blocks: ceil(50000/1024)

static const size_t SL  = (size_t)NN * CH;
static const size_t SLK = (size_t)NN * KB;

// ---------------- static scratch ----------------
__device__ float  g_deg[NN];
__device__ float  g_dinv[NN];
__device__ int    g_cnt[NN];
__device__ int    g_off[NN + 1];
__device__ int    g_cur[NN];
__device__ int    g_bsum[SCB];
__device__ int    g_bpre[SCB];
__device__ int2   g_cw[NE];                         // packed {col, w-bits}
__device__ __half g_Xh [(size_t)SEQL * NN * CH];    // fp16 X, all t
__device__ __half g_Hh [(size_t)NN * CH];           // fp16 copy of H state
__device__ __half g_HRh[(size_t)NN * CH];           // fp16 H*R
__device__ __half g_XBX[(size_t)SEQL * NN * KB];    // fp16 X basis, all t
__device__ __half g_XBH[(size_t)NN * KB];           // fp16 H/HR basis
__device__ float  g_GX [(size_t)SEQL * NN * KB];    // x-gate preactivations
__device__ float  g_Z  [(size_t)NN * CH];
__device__ __half g_BX [192 * KB];                  // fp16 transposed weights
__device__ __half g_BZR[128 * KB];
__device__ __half g_BH [64 * KB];
__device__ float  g_bX [192];
__device__ float  g_bZR[128];

// ---------------- helpers ----------------
__device__ __forceinline__ void mma_f16(float* d, const uint32_t* a, const uint32_t* b) {
    asm volatile(
        "mma.sync.aligned.m16n8k16.row.col.f32.f16.f16.f32 "
        "{%0,%1,%2,%3}, {%4,%5,%6,%7}, {%8,%9}, {%0,%1,%2,%3};\n"
        : "+f"(d[0]), "+f"(d[1]), "+f"(d[2]), "+f"(d[3])
        : "r"(a[0]), "r"(a[1]), "r"(a[2]), "r"(a[3]), "r"(b[0]), "r"(b[1]));
}

// ---------------- setup ----------------
__global__ void k_zero_setup() {
    int i = blockIdx.x * blockDim.x + threadIdx.x;
    if (i < NN) { g_deg[i] = 0.f; g_cnt[i] = 0; g_cur[i] = 0; }
}
__global__ void k_edgepre(const int* __restrict__ ei, const float* __restrict__ ew) {
    int e = blockIdx.x * blockDim.x + threadIdx.x;
    if (e < NE) {
        int r = ei[e], c = ei[NE + e];
        if (r != c) atomicAdd(&g_deg[r], ew[e]);
        atomicAdd(&g_cnt[r], 1);
    }
}
__global__ void k_dinv() {
    int i = blockIdx.x * blockDim.x + threadIdx.x;
    if (i < NN) {
        float d = g_deg[i];
        g_dinv[i] = d > 0.f ? rsqrtf(d) : 0.f;
    }
}
// 3-phase coalesced exclusive scan of g_cnt -> g_off
__global__ void k_scan1() {
    __shared__ int sh[1024];
    int b = blockIdx.x, t = threadIdx.x, idx = b * 1024 + t;
    int v = (idx < NN) ? g_cnt[idx] : 0;
    sh[t] = v; __syncthreads();
    for (int d = 1; d < 1024; d <<= 1) {
        int u = (t >= d) ? sh[t - d] : 0;
        __syncthreads(); sh[t] += u; __syncthreads();
    }
    if (idx < NN) g_off[idx] = sh[t] - v;
    if (t == 1023) g_bsum[b] = sh[1023];
}
__global__ void k_scan2() {
    __shared__ int sh[64];
    int t = threadIdx.x;
    int v = (t < SCB) ? g_bsum[t] : 0;
    sh[t] = v; __syncthreads();
    for (int d = 1; d < 64; d <<= 1) {
        int u = (t >= d) ? sh[t - d] : 0;
        __syncthreads(); sh[t] += u; __syncthreads();
    }
    if (t < SCB) g_bpre[t] = sh[t] - v;
}
__global__ void k_scan3() {
    int i = blockIdx.x * blockDim.x + threadIdx.x;
    if (i < NN) g_off[i] += g_bpre[i >> 10];
    if (i == NN) g_off[NN] = NE;
}
__global__ void k_scatter(const int* __restrict__ ei, const float* __restrict__ ew) {
    int e = blockIdx.x * blockDim.x + threadIdx.x;
    if (e < NE) {
        int r = ei[e], c = ei[NE + e];
        float w = (r == c) ? 0.f : ew[e];
        float wn = -w * g_dinv[r] * g_dinv[c];
        int pos = g_off[r] + atomicAdd(&g_cur[r], 1);
        g_cw[pos] = make_int2(c, __float_as_int(wn));
    }
}
// transposed fp16 weights B[n_out][k], k = cheb*64+cin; concat biases
__global__ void k_prepB(const float* __restrict__ Wxz, const float* __restrict__ Wxr,
                        const float* __restrict__ Wxh, const float* __restrict__ Whz,
                        const float* __restrict__ Whr, const float* __restrict__ Whh,
                        const float* __restrict__ bxz, const float* __restrict__ bxr,
                        const float* __restrict__ bxh, const float* __restrict__ bhz,
                        const float* __restrict__ bhr) {
    int i = blockIdx.x * blockDim.x + threadIdx.x;
    if (i < 192 * KB) {
        int n = i / KB, k = i % KB, kc = k / 64, ci = k & 63, gate = n / 64, c = n & 63;
        const float* W = gate == 0 ? Wxz : (gate == 1 ? Wxr : Wxh);
        g_BX[i] = __float2half(W[kc * 4096 + ci * 64 + c]);
    }
    if (i < 128 * KB) {
        int n = i / KB, k = i % KB, kc = k / 64, ci = k & 63, c = n & 63;
        const float* W = n < 64 ? Whz : Whr;
        g_BZR[i] = __float2half(W[kc * 4096 + ci * 64 + c]);
    }
    if (i < 64 * KB) {
        int n = i / KB, k = i % KB, kc = k / 64, ci = k & 63;
        g_BH[i] = __float2half(Whh[kc * 4096 + ci * 64 + (n & 63)]);
    }
    if (i < 192) g_bX[i] = i < 64 ? bxz[i] : (i < 128 ? bxr[i - 64] : bxh[i - 128]);
    if (i < 128) g_bZR[i] = i < 64 ? bhz[i] : bhr[i - 64];
}
// X fp32 -> fp16
__global__ void k_x2h(const float* __restrict__ X, int n4) {
    int i = blockIdx.x * blockDim.x + threadIdx.x;
    if (i < n4) {
        float4 v = ((const float4*)X)[i];
        __half2 h0 = __floats2half2_rn(v.x, v.y);
        __half2 h1 = __floats2half2_rn(v.z, v.w);
        ((uint2*)g_Xh)[i] = make_uint2(*(uint32_t*)&h0, *(uint32_t*)&h1);
    }
}

// ---------------- SpMM (quarter-warp per edge, fp16 rows, fp32 accum) ------
// spmmA: XB[:,0:64] = vh (copy); XB[:,64:128] = h(S @ vh)
__global__ void k_spmmA(const __half* __restrict__ vh, __half* __restrict__ XB) {
    int warp = (blockIdx.x * blockDim.x + threadIdx.x) >> 5;
    if (warp >= NN) return;
    int lane = threadIdx.x & 31, sub = lane >> 3, cg = lane & 7;
    const uint4* v4 = (const uint4*)(vh + (size_t)blockIdx.y * SL);
    int s = g_off[warp], e = g_off[warp + 1];
    float acc[8];
#pragma unroll
    for (int k = 0; k < 8; k++) acc[k] = 0.f;
    for (int j = s + sub; j < e; j += 4) {
        int2 cw = g_cw[j];
        float w = __int_as_float(cw.y);
        uint4 u = v4[(size_t)cw.x * 8 + cg];
        const __half2* h = (const __half2*)&u;
#pragma unroll
        for (int k = 0; k < 4; k++) {
            float2 f = __half22float2(h[k]);
            acc[2 * k]     += w * f.x;
            acc[2 * k + 1] += w * f.y;
        }
    }
#pragma unroll
    for (int d = 8; d <= 16; d <<= 1)
#pragma unroll
        for (int k = 0; k < 8; k++)
            acc[k] += __shfl_xor_sync(0xffffffffu, acc[k], d);
    if (sub == 0) {
        uint4* o = (uint4*)(XB + (size_t)blockIdx.y * SLK + (size_t)warp * KB);
        o[cg] = v4[(size_t)warp * 8 + cg];        // T0 = copy
        uint4 r; __half2* rh = (__half2*)&r;
#pragma unroll
        for (int k = 0; k < 4; k++) rh[k] = __floats2half2_rn(acc[2 * k], acc[2 * k + 1]);
        o[8 + cg] = r;                            // T1
    }
}
// spmmB: XB[:,128:192] = h(2 * (S @ T1) - T0)
__global__ void k_spmmB(__half* __restrict__ XB) {
    int warp = (blockIdx.x * blockDim.x + threadIdx.x) >> 5;
    if (warp >= NN) return;
    int lane = threadIdx.x & 31, sub = lane >> 3, cg = lane & 7;
    uint4* x4 = (uint4*)(XB + (size_t)blockIdx.y * SLK);
    int s = g_off[warp], e = g_off[warp + 1];
    float acc[8];
#pragma unroll
    for (int k = 0; k < 8; k++) acc[k] = 0.f;
    for (int j = s + sub; j < e; j += 4) {
        int2 cw = g_cw[j];
        float w = __int_as_float(cw.y);
        uint4 u = x4[(size_t)cw.x * 24 + 8 + cg];
        const __half2* h = (const __half2*)&u;
#pragma unroll
        for (int k = 0; k < 4; k++) {
            float2 f = __half22float2(h[k]);
            acc[2 * k]     += w * f.x;
            acc[2 * k + 1] += w * f.y;
        }
    }
#pragma unroll
    for (int d = 8; d <= 16; d <<= 1)
#pragma unroll
        for (int k = 0; k < 8; k++)
            acc[k] += __shfl_xor_sync(0xffffffffu, acc[k], d);
    if (sub == 0) {
        uint4* o = x4 + (size_t)warp * 24;
        uint4 t0u = o[cg];
        const __half2* th = (const __half2*)&t0u;
        uint4 r; __half2* rh = (__half2*)&r;
#pragma unroll
        for (int k = 0; k < 4; k++) {
            float2 tf = __half22float2(th[k]);
            rh[k] = __floats2half2_rn(2.f * acc[2 * k] - tf.x,
                                      2.f * acc[2 * k + 1] - tf.y);
        }
        o[16 + cg] = r;                           // T2
    }
}

// ---------------- fp16 mma.sync GEMM, fused epilogues ----------------
// D[128 x NOUT] = A[128 x 192]h @ B[NOUT x 192]h^T, fp32 accum.
// EPI 0: out[r*192+c] = acc + bias                                   (GX)
// EPI 1: c<64: Z fp32; c>=64: HRh = h(H * sigmoid(...))
// EPI 2: Ht = tanh(...); out fp32 = Z*H+(1-Z)*Ht; outh = h(out)
#define PADH 72

template <int NOUT, int EPI>
__global__ void __launch_bounds__(128 * (NOUT / 64)) k_mgemm(
    const __half* __restrict__ A, const __half* __restrict__ B,
    const float* __restrict__ bias, const float* __restrict__ GX,
    const float* __restrict__ H, const float* __restrict__ Z,
    float* __restrict__ out, __half* __restrict__ outh, int rows,
    size_t ayStride, size_t oyStride)
{
    __shared__ __half As[128 * PADH];
    __shared__ __half Bs[NOUT * PADH];

    A   += (size_t)blockIdx.y * ayStride;
    out += (size_t)blockIdx.y * oyStride;

    const int NTH = 128 * (NOUT / 64);
    int tid = threadIdx.x;
    int wid = tid >> 5, lane = tid & 31;
    int mw = wid & 3, nw = wid >> 2;
    int g = lane >> 2, tq = lane & 3;
    int rb = blockIdx.x * 128;

    float acc[2][8][4];
#pragma unroll
    for (int mt = 0; mt < 2; mt++)
#pragma unroll
        for (int nt = 0; nt < 8; nt++)
#pragma unroll
            for (int q = 0; q < 4; q++) acc[mt][nt][q] = 0.f;

    for (int kc = 0; kc < 3; kc++) {    // k-chunks of 64 halves
        // stage A tile: 128 rows x 64 halves = 1024 uint4 slots
#pragma unroll
        for (int idx = tid; idx < 1024; idx += NTH) {
            int row = idx >> 3, q = idx & 7;
            uint4 v = make_uint4(0u, 0u, 0u, 0u);
            int gr = rb + row;
            if (gr < rows) v = *(const uint4*)(A + (size_t)gr * KB + kc * 64 + q * 8);
            *(uint4*)&As[row * PADH + q * 8] = v;
        }
#pragma unroll
        for (int idx = tid; idx < NOUT * 8; idx += NTH) {
            int row = idx >> 3, q = idx & 7;
            uint4 v = *(const uint4*)(B + (size_t)row * KB + kc * 64 + q * 8);
            *(uint4*)&Bs[row * PADH + q * 8] = v;
        }
        __syncthreads();
#pragma unroll
        for (int kk = 0; kk < 4; kk++) {     // 4 x k16
            int kb = kk * 16 + tq * 2;
            uint32_t a[2][4];
#pragma unroll
            for (int mt = 0; mt < 2; mt++) {
                int r = mw * 32 + mt * 16 + g;
                a[mt][0] = *(const uint32_t*)&As[r * PADH + kb];
                a[mt][1] = *(const uint32_t*)&As[(r + 8) * PADH + kb];
                a[mt][2] = *(const uint32_t*)&As[r * PADH + kb + 8];
                a[mt][3] = *(const uint32_t*)&As[(r + 8) * PADH + kb + 8];
            }
            uint32_t b[8][2];
#pragma unroll
            for (int nt = 0; nt < 8; nt++) {
                int n = nw * 64 + nt * 8 + g;
                b[nt][0] = *(const uint32_t*)&Bs[n * PADH + kb];
                b[nt][1] = *(const uint32_t*)&Bs[n * PADH + kb + 8];
            }
#pragma unroll
            for (int mt = 0; mt < 2; mt++)
#pragma unroll
                for (int nt = 0; nt < 8; nt++)
                    mma_f16(acc[mt][nt], a[mt], b[nt]);
        }
        __syncthreads();
    }

    // epilogue
#pragma unroll
    for (int mt = 0; mt < 2; mt++) {
#pragma unroll
        for (int nt = 0; nt < 8; nt++) {
            int c = nw * 64 + nt * 8 + tq * 2;
            float bx = bias[c], by = bias[c + 1];
#pragma unroll
            for (int hh = 0; hh < 2; hh++) {
                int r = rb + mw * 32 + mt * 16 + g + hh * 8;
                if (r >= rows) continue;
                float vx = acc[mt][nt][hh * 2] + bx;
                float vy = acc[mt][nt][hh * 2 + 1] + by;
                if (EPI == 0) {
                    *(float2*)(out + (size_t)r * KB + c) = make_float2(vx, vy);
                } else if (EPI == 1) {
                    float2 gx = *(const float2*)(GX + (size_t)r * KB + c);
                    float sx = 1.f / (1.f + expf(-(vx + gx.x)));
                    float sy = 1.f / (1.f + expf(-(vy + gx.y)));
                    if (c < 64) {
                        *(float2*)(out + (size_t)r * CH + c) = make_float2(sx, sy);
                    } else {
                        float2 h = *(const float2*)(H + (size_t)r * CH + (c - 64));
                        __half2 hv = __floats2half2_rn(h.x * sx, h.y * sy);
                        *(__half2*)(outh + (size_t)r * CH + (c - 64)) = hv;
                    }
                } else {
                    float2 gx = *(const float2*)(GX + (size_t)r * KB + 128 + c);
                    float2 h  = *(const float2*)(H + (size_t)r * CH + c);
                    float2 z2 = *(const float2*)(Z + (size_t)r * CH + c);
                    float tx = tanhf(vx + gx.x), ty = tanhf(vy + gx.y);
                    float ox = z2.x * h.x + (1.f - z2.x) * tx;
                    float oy = z2.y * h.y + (1.f - z2.y) * ty;
                    *(float2*)(out + (size_t)r * CH + c) = make_float2(ox, oy);
                    *(__half2*)(outh + (size_t)r * CH + c) = __floats2half2_rn(ox, oy);
                }
            }
        }
    }
}

// t = 0: H0 = 0 => Hn = (1 - sigmoid(GXz + b_hz)) * tanh(GXh + b_hh)
__global__ void k_t0(const float* __restrict__ GX, const float* __restrict__ bhz,
                     const float* __restrict__ bhh, float* __restrict__ out) {
    int i = blockIdx.x * blockDim.x + threadIdx.x;
    if (i >= NN * CH) return;
    int r = i >> 6, c = i & 63;
    float z  = 1.f / (1.f + expf(-(GX[(size_t)r * KB + c] + bhz[c])));
    float ht = tanhf(GX[(size_t)r * KB + 128 + c] + bhh[c]);
    float res = (1.f - z) * ht;
    out[i] = res;
    g_Hh[i] = __float2half(res);
}

__global__ void k_copy(const float* __restrict__ src, float* __restrict__ dst, int n) {
    int i = blockIdx.x * blockDim.x + threadIdx.x;
    if (i < n) dst[i] = src[i];
}

// ---------------- host side ----------------
extern "C" void kernel_launch(void* const* d_in, const int* in_sizes, int n_in,
                              void* d_out, int out_size) {
    const float* X    = (const float*)d_in[0];
    const int*   ei   = (const int*)  d_in[1];
    const float* ew   = (const float*)d_in[2];
    const float* W_xz = (const float*)d_in[3];
    const float* b_xz = (const float*)d_in[4];
    const float* W_hz = (const float*)d_in[5];
    const float* b_hz = (const float*)d_in[6];
    const float* W_xr = (const float*)d_in[7];
    const float* b_xr = (const float*)d_in[8];
    const float* W_hr = (const float*)d_in[9];
    const float* b_hr = (const float*)d_in[10];
    const float* W_xh = (const float*)d_in[11];
    const float* b_xh = (const float*)d_in[12];
    const float* W_hh = (const float*)d_in[13];
    const float* b_hh = (const float*)d_in[14];
    float* out = (float*)d_out;

    __half *pXh, *pHh, *pHRh, *pXBX, *pXBH, *pBX, *pBZR, *pBH;
    float  *pGX, *pZ, *pbX, *pbZR;
    cudaGetSymbolAddress((void**)&pXh,  g_Xh);
    cudaGetSymbolAddress((void**)&pHh,  g_Hh);
    cudaGetSymbolAddress((void**)&pHRh, g_HRh);
    cudaGetSymbolAddress((void**)&pXBX, g_XBX);
    cudaGetSymbolAddress((void**)&pXBH, g_XBH);
    cudaGetSymbolAddress((void**)&pGX,  g_GX);
    cudaGetSymbolAddress((void**)&pZ,   g_Z);
    cudaGetSymbolAddress((void**)&pBX,  g_BX);
    cudaGetSymbolAddress((void**)&pBZR, g_BZR);
    cudaGetSymbolAddress((void**)&pBH,  g_BH);
    cudaGetSymbolAddress((void**)&pbX,  g_bX);
    cudaGetSymbolAddress((void**)&pbZR, g_bZR);

    const int NB_NODE = (NN + 255) / 256;
    const int NB_EDGE = (NE + 255) / 256;
    const int NB_SPMM = (NN * 32 + 255) / 256;
    const int NB_GEMM = (NN + 127) / 128;
    const int NX4 = SEQL * NN * CH / 4;

    // setup: normalization + CSR + weights + fp16 X
    k_zero_setup<<<NB_NODE, 256>>>();
    k_edgepre<<<NB_EDGE, 256>>>(ei, ew);
    k_dinv<<<NB_NODE, 256>>>();
    k_scan1<<<SCB, 1024>>>();
    k_scan2<<<1, 64>>>();
    k_scan3<<<(NN + 256) / 256, 256>>>();
    k_scatter<<<NB_EDGE, 256>>>(ei, ew);
    k_prepB<<<(192 * KB + 255) / 256, 256>>>(W_xz, W_xr, W_xh, W_hz, W_hr, W_hh,
                                             b_xz, b_xr, b_xh, b_hz, b_hr);
    k_x2h<<<(NX4 + 255) / 256, 256>>>(X, NX4);

    // X-stage for all timesteps (3 batched launches)
    {
        dim3 gs(NB_SPMM, SEQL), gg(NB_GEMM, SEQL);
        k_spmmA<<<gs, 256>>>(pXh, pXBX);
        k_spmmB<<<gs, 256>>>(pXBX);
        k_mgemm<192, 0><<<gg, 384>>>(pXBX, pBX, pbX, nullptr, nullptr, nullptr,
                                     pGX, nullptr, NN, SLK, SLK);
    }

    // t = 0 shortcut (H0 = 0)
    k_t0<<<(NN * CH + 255) / 256, 256>>>(pGX, b_hz, b_hh, out);

    // t = 1..7 recurrent chain
    for (int t = 1; t < SEQL; t++) {
        const float* Hp  = out + (size_t)(t - 1) * SL;
        const float* GXt = pGX + (size_t)t * SLK;
        float* Ot = out + (size_t)t * SL;

        k_spmmA<<<NB_SPMM, 256>>>(pHh, pXBH);
        k_spmmB<<<NB_SPMM, 256>>>(pXBH);
        k_mgemm<128, 1><<<NB_GEMM, 256>>>(pXBH, pBZR, pbZR, GXt, Hp, nullptr,
                                          pZ, pHRh, NN, 0, 0);
        k_spmmA<<<NB_SPMM, 256>>>(pHRh, pXBH);
        k_spmmB<<<NB_SPMM, 256>>>(pXBH);
        k_mgemm<64, 2><<<NB_GEMM, 128>>>(pXBH, pBH, b_hh, GXt, Hp, pZ,
                                         Ot, pHh, NN, 0, 0);
    }

    // Hlast = States[:, -1]
    if (out_size >= (int)((SEQL + 1) * SL)) {
        int n = (int)SL;
        k_copy<<<(n + 255) / 256, 256>>>(out + (size_t)(SEQL - 1) * SL,
                                         out + (size_t)SEQL * SL, n);
    }
}

// round 13
// speedup vs baseline: 1.2824x; 1.0150x over previous
#include <cuda_runtime.h>
#include <cuda_fp16.h>
#include <math.h>
#include <cstdint>

#define NN 50000
#define NE 800000
#define CH 64
#define SEQL 8
#define KB 192
#define SCB 49
#define PADH 72

static const size_t SL  = (size_t)NN * CH;
static const size_t SLK = (size_t)NN * KB;

// ---------------- static scratch ----------------
__device__ float  g_deg[NN];
__device__ float  g_dinv[NN];
__device__ int    g_cnt[NN];
__device__ int    g_off[NN + 1];
__device__ int    g_cur[NN];
__device__ int    g_bsum[SCB];
__device__ int    g_bpre[SCB];
__device__ int2   g_cw[NE];                      // packed {col, w-bits}
__device__ __half g_Xh [(size_t)SEQL * NN * CH]; // fp16 X, all t
__device__ __half g_Hh [(size_t)NN * CH];        // fp16 H state
__device__ __half g_HRh[(size_t)NN * CH];        // fp16 H*R
__device__ __half g_T1X[(size_t)NN * CH];        // T1 buffer (X pipeline, stream s1)
__device__ __half g_T1H[(size_t)NN * CH];        // T1 buffer (H chain)
__device__ float  g_GX [(size_t)SEQL * NN * KB]; // x-gate preactivations
__device__ float  g_Z  [(size_t)NN * CH];
__device__ __half g_BX [192 * KB];               // fp16 transposed weights
__device__ __half g_BZR[128 * KB];
__device__ __half g_BH [64 * KB];
__device__ float  g_bX [192];
__device__ float  g_bZR[128];

// ---------------- helpers ----------------
__device__ __forceinline__ void mma_f16(float* d, const uint32_t* a, const uint32_t* b) {
    asm volatile(
        "mma.sync.aligned.m16n8k16.row.col.f32.f16.f16.f32 "
        "{%0,%1,%2,%3}, {%4,%5,%6,%7}, {%8,%9}, {%0,%1,%2,%3};\n"
        : "+f"(d[0]), "+f"(d[1]), "+f"(d[2]), "+f"(d[3])
        : "r"(a[0]), "r"(a[1]), "r"(a[2]), "r"(a[3]), "r"(b[0]), "r"(b[1]));
}

// ---------------- setup ----------------
__global__ void k_zero_setup() {
    int i = blockIdx.x * blockDim.x + threadIdx.x;
    if (i < NN) { g_deg[i] = 0.f; g_cnt[i] = 0; g_cur[i] = 0; }
}
__global__ void k_edgepre(const int* __restrict__ ei, const float* __restrict__ ew) {
    int e = blockIdx.x * blockDim.x + threadIdx.x;
    if (e < NE) {
        int r = ei[e], c = ei[NE + e];
        if (r != c) atomicAdd(&g_deg[r], ew[e]);
        atomicAdd(&g_cnt[r], 1);
    }
}
__global__ void k_dinv() {
    int i = blockIdx.x * blockDim.x + threadIdx.x;
    if (i < NN) {
        float d = g_deg[i];
        g_dinv[i] = d > 0.f ? rsqrtf(d) : 0.f;
    }
}
__global__ void k_scan1() {
    __shared__ int sh[1024];
    int b = blockIdx.x, t = threadIdx.x, idx = b * 1024 + t;
    int v = (idx < NN) ? g_cnt[idx] : 0;
    sh[t] = v; __syncthreads();
    for (int d = 1; d < 1024; d <<= 1) {
        int u = (t >= d) ? sh[t - d] : 0;
        __syncthreads(); sh[t] += u; __syncthreads();
    }
    if (idx < NN) g_off[idx] = sh[t] - v;
    if (t == 1023) g_bsum[b] = sh[1023];
}
__global__ void k_scan2() {
    __shared__ int sh[64];
    int t = threadIdx.x;
    int v = (t < SCB) ? g_bsum[t] : 0;
    sh[t] = v; __syncthreads();
    for (int d = 1; d < 64; d <<= 1) {
        int u = (t >= d) ? sh[t - d] : 0;
        __syncthreads(); sh[t] += u; __syncthreads();
    }
    if (t < SCB) g_bpre[t] = sh[t] - v;
}
__global__ void k_scan3() {
    int i = blockIdx.x * blockDim.x + threadIdx.x;
    if (i < NN) g_off[i] += g_bpre[i >> 10];
    if (i == NN) g_off[NN] = NE;
}
__global__ void k_scatter(const int* __restrict__ ei, const float* __restrict__ ew) {
    int e = blockIdx.x * blockDim.x + threadIdx.x;
    if (e < NE) {
        int r = ei[e], c = ei[NE + e];
        float w = (r == c) ? 0.f : ew[e];
        float wn = -w * g_dinv[r] * g_dinv[c];
        int pos = g_off[r] + atomicAdd(&g_cur[r], 1);
        g_cw[pos] = make_int2(c, __float_as_int(wn));
    }
}
__global__ void k_prepB(const float* __restrict__ Wxz, const float* __restrict__ Wxr,
                        const float* __restrict__ Wxh, const float* __restrict__ Whz,
                        const float* __restrict__ Whr, const float* __restrict__ Whh,
                        const float* __restrict__ bxz, const float* __restrict__ bxr,
                        const float* __restrict__ bxh, const float* __restrict__ bhz,
                        const float* __restrict__ bhr) {
    int i = blockIdx.x * blockDim.x + threadIdx.x;
    if (i < 192 * KB) {
        int n = i / KB, k = i % KB, kc = k / 64, ci = k & 63, gate = n / 64, c = n & 63;
        const float* W = gate == 0 ? Wxz : (gate == 1 ? Wxr : Wxh);
        g_BX[i] = __float2half(W[kc * 4096 + ci * 64 + c]);
    }
    if (i < 128 * KB) {
        int n = i / KB, k = i % KB, kc = k / 64, ci = k & 63, c = n & 63;
        const float* W = n < 64 ? Whz : Whr;
        g_BZR[i] = __float2half(W[kc * 4096 + ci * 64 + c]);
    }
    if (i < 64 * KB) {
        int n = i / KB, k = i % KB, kc = k / 64, ci = k & 63;
        g_BH[i] = __float2half(Whh[kc * 4096 + ci * 64 + (n & 63)]);
    }
    if (i < 192) g_bX[i] = i < 64 ? bxz[i] : (i < 128 ? bxr[i - 64] : bxh[i - 128]);
    if (i < 128) g_bZR[i] = i < 64 ? bhz[i] : bhr[i - 64];
}
__global__ void k_x2h(const float* __restrict__ X, int n4) {
    int i = blockIdx.x * blockDim.x + threadIdx.x;
    if (i < n4) {
        float4 v = ((const float4*)X)[i];
        __half2 h0 = __floats2half2_rn(v.x, v.y);
        __half2 h1 = __floats2half2_rn(v.z, v.w);
        ((uint2*)g_Xh)[i] = make_uint2(*(uint32_t*)&h0, *(uint32_t*)&h1);
    }
}

// ---------------- SpMM: T1 = S @ vh (quarter-warp per edge) ----------------
__global__ void k_spmmT1(const __half* __restrict__ vh, __half* __restrict__ T1) {
    int warp = (blockIdx.x * blockDim.x + threadIdx.x) >> 5;
    if (warp >= NN) return;
    int lane = threadIdx.x & 31, sub = lane >> 3, cg = lane & 7;
    const uint4* v4 = (const uint4*)vh;
    int s = g_off[warp], e = g_off[warp + 1];
    float acc[8];
#pragma unroll
    for (int k = 0; k < 8; k++) acc[k] = 0.f;
    for (int j = s + sub; j < e; j += 4) {
        int2 cw = g_cw[j];
        float w = __int_as_float(cw.y);
        uint4 u = v4[(size_t)cw.x * 8 + cg];
        const __half2* h = (const __half2*)&u;
#pragma unroll
        for (int k = 0; k < 4; k++) {
            float2 f = __half22float2(h[k]);
            acc[2 * k]     += w * f.x;
            acc[2 * k + 1] += w * f.y;
        }
    }
#pragma unroll
    for (int d = 8; d <= 16; d <<= 1)
#pragma unroll
        for (int k = 0; k < 8; k++)
            acc[k] += __shfl_xor_sync(0xffffffffu, acc[k], d);
    if (sub == 0) {
        uint4 r; __half2* rh = (__half2*)&r;
#pragma unroll
        for (int k = 0; k < 4; k++) rh[k] = __floats2half2_rn(acc[2 * k], acc[2 * k + 1]);
        ((uint4*)T1)[(size_t)warp * 8 + cg] = r;
    }
}

// ---------------- fused GEMM: T2-gather prologue + fp16 MMA + epilogues ----
// acc = T0@W0 + T1@W1 + T2@W2, T2 = 2*(S@T1) - T0 computed into smem.
// EPI 0: out[r*KB+c] = acc + bias                                    (GX)
// EPI 1: c<64: Z fp32; c>=64: outh = h(H * sigmoid(acc+bias+GX))
// EPI 2: Ht = tanh(acc+bias+GX[128+]); out = Z*H+(1-Z)*Ht; outh = h(out)
template <int NOUT, int EPI>
__global__ void __launch_bounds__(128 * (NOUT / 64)) k_fgemm(
    const __half* __restrict__ T0, const __half* __restrict__ T1,
    const __half* __restrict__ B, const float* __restrict__ bias,
    const float* __restrict__ GX, const float* __restrict__ H,
    const float* __restrict__ Z, float* __restrict__ out,
    __half* __restrict__ outh, int rows)
{
    extern __shared__ __half sm[];
    __half* As  = sm;                  // 128 * PADH
    __half* T2s = As + 128 * PADH;     // 128 * PADH
    __half* Bs  = T2s + 128 * PADH;    // NOUT * PADH

    const int NTH = 128 * (NOUT / 64);
    const int NW  = NTH / 32;
    int tid = threadIdx.x;
    int wid = tid >> 5, lane = tid & 31;
    int mw = wid & 3, nw = wid >> 2;
    int g = lane >> 2, tq = lane & 3;
    int sub = lane >> 3, cg = lane & 7;
    int rb = blockIdx.x * 128;

    // ---- prologue: gather T2 = 2*(S@T1) - T0 for this block's rows ----
    for (int row = wid; row < 128; row += NW) {
        int gr = rb + row;
        float acc[8];
#pragma unroll
        for (int k = 0; k < 8; k++) acc[k] = 0.f;
        if (gr < rows) {
            int s = g_off[gr], e = g_off[gr + 1];
            for (int j = s + sub; j < e; j += 4) {
                int2 cw = g_cw[j];
                float w = __int_as_float(cw.y);
                uint4 u = *(const uint4*)(T1 + (size_t)cw.x * CH + cg * 8);
                const __half2* h = (const __half2*)&u;
#pragma unroll
                for (int k = 0; k < 4; k++) {
                    float2 f = __half22float2(h[k]);
                    acc[2 * k]     += w * f.x;
                    acc[2 * k + 1] += w * f.y;
                }
            }
        }
#pragma unroll
        for (int d = 8; d <= 16; d <<= 1)
#pragma unroll
            for (int k = 0; k < 8; k++)
                acc[k] += __shfl_xor_sync(0xffffffffu, acc[k], d);
        if (sub == 0) {
            uint4 t0u = make_uint4(0u, 0u, 0u, 0u);
            if (gr < rows) t0u = *(const uint4*)(T0 + (size_t)gr * CH + cg * 8);
            const __half2* th = (const __half2*)&t0u;
            uint4 r; __half2* rh = (__half2*)&r;
#pragma unroll
            for (int k = 0; k < 4; k++) {
                float2 tf = __half22float2(th[k]);
                rh[k] = __floats2half2_rn(2.f * acc[2 * k] - tf.x,
                                          2.f * acc[2 * k + 1] - tf.y);
            }
            *(uint4*)&T2s[row * PADH + cg * 8] = r;
        }
    }
    __syncthreads();

    // ---- main loop: 3 k-chunks of 64 halves ----
    float acc[2][8][4];
#pragma unroll
    for (int mt = 0; mt < 2; mt++)
#pragma unroll
        for (int nt = 0; nt < 8; nt++)
#pragma unroll
            for (int q = 0; q < 4; q++) acc[mt][nt][q] = 0.f;

    for (int kc = 0; kc < 3; kc++) {
        if (kc < 2) {
            const __half* Asrc = (kc == 0) ? T0 : T1;
#pragma unroll
            for (int idx = tid; idx < 1024; idx += NTH) {
                int row = idx >> 3, q = idx & 7;
                uint4 v = make_uint4(0u, 0u, 0u, 0u);
                int gr = rb + row;
                if (gr < rows) v = *(const uint4*)(Asrc + (size_t)gr * CH + q * 8);
                *(uint4*)&As[row * PADH + q * 8] = v;
            }
        }
#pragma unroll
        for (int idx = tid; idx < NOUT * 8; idx += NTH) {
            int row = idx >> 3, q = idx & 7;
            uint4 v = *(const uint4*)(B + (size_t)row * KB + kc * 64 + q * 8);
            *(uint4*)&Bs[row * PADH + q * 8] = v;
        }
        __syncthreads();
        const __half* At = (kc == 2) ? T2s : As;
#pragma unroll
        for (int kk = 0; kk < 4; kk++) {
            int kb = kk * 16 + tq * 2;
            uint32_t a[2][4];
#pragma unroll
            for (int mt = 0; mt < 2; mt++) {
                int r = mw * 32 + mt * 16 + g;
                a[mt][0] = *(const uint32_t*)&At[r * PADH + kb];
                a[mt][1] = *(const uint32_t*)&At[(r + 8) * PADH + kb];
                a[mt][2] = *(const uint32_t*)&At[r * PADH + kb + 8];
                a[mt][3] = *(const uint32_t*)&At[(r + 8) * PADH + kb + 8];
            }
            uint32_t b[8][2];
#pragma unroll
            for (int nt = 0; nt < 8; nt++) {
                int n = nw * 64 + nt * 8 + g;
                b[nt][0] = *(const uint32_t*)&Bs[n * PADH + kb];
                b[nt][1] = *(const uint32_t*)&Bs[n * PADH + kb + 8];
            }
#pragma unroll
            for (int mt = 0; mt < 2; mt++)
#pragma unroll
                for (int nt = 0; nt < 8; nt++)
                    mma_f16(acc[mt][nt], a[mt], b[nt]);
        }
        __syncthreads();
    }

    // ---- epilogue ----
#pragma unroll
    for (int mt = 0; mt < 2; mt++) {
#pragma unroll
        for (int nt = 0; nt < 8; nt++) {
            int c = nw * 64 + nt * 8 + tq * 2;
            float bx = bias[c], by = bias[c + 1];
#pragma unroll
            for (int hh = 0; hh < 2; hh++) {
                int r = rb + mw * 32 + mt * 16 + g + hh * 8;
                if (r >= rows) continue;
                float vx = acc[mt][nt][hh * 2] + bx;
                float vy = acc[mt][nt][hh * 2 + 1] + by;
                if (EPI == 0) {
                    *(float2*)(out + (size_t)r * KB + c) = make_float2(vx, vy);
                } else if (EPI == 1) {
                    float2 gx = *(const float2*)(GX + (size_t)r * KB + c);
                    float sx = 1.f / (1.f + expf(-(vx + gx.x)));
                    float sy = 1.f / (1.f + expf(-(vy + gx.y)));
                    if (c < 64) {
                        *(float2*)(out + (size_t)r * CH + c) = make_float2(sx, sy);
                    } else {
                        float2 h = *(const float2*)(H + (size_t)r * CH + (c - 64));
                        *(__half2*)(outh + (size_t)r * CH + (c - 64)) =
                            __floats2half2_rn(h.x * sx, h.y * sy);
                    }
                } else {
                    float2 gx = *(const float2*)(GX + (size_t)r * KB + 128 + c);
                    float2 h  = *(const float2*)(H + (size_t)r * CH + c);
                    float2 z2 = *(const float2*)(Z + (size_t)r * CH + c);
                    float tx = tanhf(vx + gx.x), ty = tanhf(vy + gx.y);
                    float ox = z2.x * h.x + (1.f - z2.x) * tx;
                    float oy = z2.y * h.y + (1.f - z2.y) * ty;
                    *(float2*)(out + (size_t)r * CH + c) = make_float2(ox, oy);
                    *(__half2*)(outh + (size_t)r * CH + c) = __floats2half2_rn(ox, oy);
                }
            }
        }
    }
}

// t = 0: H0 = 0 => Hn = (1 - sigmoid(GXz + b_hz)) * tanh(GXh + b_hh)
__global__ void k_t0(const float* __restrict__ GX, const float* __restrict__ bhz,
                     const float* __restrict__ bhh, float* __restrict__ out) {
    int i = blockIdx.x * blockDim.x + threadIdx.x;
    if (i >= NN * CH) return;
    int r = i >> 6, c = i & 63;
    float z  = 1.f / (1.f + expf(-(GX[(size_t)r * KB + c] + bhz[c])));
    float ht = tanhf(GX[(size_t)r * KB + 128 + c] + bhh[c]);
    float res = (1.f - z) * ht;
    out[i] = res;
    g_Hh[i] = __float2half(res);
}

__global__ void k_copy(const float* __restrict__ src, float* __restrict__ dst, int n) {
    int i = blockIdx.x * blockDim.x + threadIdx.x;
    if (i < n) dst[i] = src[i];
}

// ---------------- host side ----------------
extern "C" void kernel_launch(void* const* d_in, const int* in_sizes, int n_in,
                              void* d_out, int out_size) {
    const float* X    = (const float*)d_in[0];
    const int*   ei   = (const int*)  d_in[1];
    const float* ew   = (const float*)d_in[2];
    const float* W_xz = (const float*)d_in[3];
    const float* b_xz = (const float*)d_in[4];
    const float* W_hz = (const float*)d_in[5];
    const float* b_hz = (const float*)d_in[6];
    const float* W_xr = (const float*)d_in[7];
    const float* b_xr = (const float*)d_in[8];
    const float* W_hr = (const float*)d_in[9];
    const float* b_hr = (const float*)d_in[10];
    const float* W_xh = (const float*)d_in[11];
    const float* b_xh = (const float*)d_in[12];
    const float* W_hh = (const float*)d_in[13];
    const float* b_hh = (const float*)d_in[14];
    float* out = (float*)d_out;

    __half *pXh, *pHh, *pHRh, *pT1X, *pT1H, *pBX, *pBZR, *pBH;
    float  *pGX, *pZ, *pbX, *pbZR;
    cudaGetSymbolAddress((void**)&pXh,  g_Xh);
    cudaGetSymbolAddress((void**)&pHh,  g_Hh);
    cudaGetSymbolAddress((void**)&pHRh, g_HRh);
    cudaGetSymbolAddress((void**)&pT1X, g_T1X);
    cudaGetSymbolAddress((void**)&pT1H, g_T1H);
    cudaGetSymbolAddress((void**)&pGX,  g_GX);
    cudaGetSymbolAddress((void**)&pZ,   g_Z);
    cudaGetSymbolAddress((void**)&pBX,  g_BX);
    cudaGetSymbolAddress((void**)&pBZR, g_BZR);
    cudaGetSymbolAddress((void**)&pBH,  g_BH);
    cudaGetSymbolAddress((void**)&pbX,  g_bX);
    cudaGetSymbolAddress((void**)&pbZR, g_bZR);

    const int NB_NODE = (NN + 255) / 256;
    const int NB_EDGE = (NE + 255) / 256;
    const int NB_SPMM = (NN * 32 + 255) / 256;
    const int NB_GEMM = (NN + 127) / 128;
    const int NX4 = SEQL * NN * CH / 4;
    const int SM192 = (128 * 2 + 192) * PADH * sizeof(__half);
    const int SM128 = (128 * 2 + 128) * PADH * sizeof(__half);
    const int SM64  = (128 * 2 + 64)  * PADH * sizeof(__half);

    cudaFuncSetAttribute(k_fgemm<192, 0>, cudaFuncAttributeMaxDynamicSharedMemorySize, SM192);
    cudaFuncSetAttribute(k_fgemm<128, 1>, cudaFuncAttributeMaxDynamicSharedMemorySize, SM128);
    cudaFuncSetAttribute(k_fgemm<64, 2>,  cudaFuncAttributeMaxDynamicSharedMemorySize, SM64);

    // setup on default stream
    k_zero_setup<<<NB_NODE, 256>>>();
    k_edgepre<<<NB_EDGE, 256>>>(ei, ew);
    k_dinv<<<NB_NODE, 256>>>();
    k_scan1<<<SCB, 1024>>>();
    k_scan2<<<1, 64>>>();
    k_scan3<<<(NN + 256) / 256, 256>>>();
    k_scatter<<<NB_EDGE, 256>>>(ei, ew);
    k_prepB<<<(192 * KB + 255) / 256, 256>>>(W_xz, W_xr, W_xh, W_hz, W_hr, W_hh,
                                             b_xz, b_xr, b_xh, b_hz, b_hr);
    k_x2h<<<(NX4 + 255) / 256, 256>>>(X, NX4);

    // fork side stream for the per-t X pipeline
    cudaStream_t s1;
    cudaStreamCreateWithFlags(&s1, cudaStreamNonBlocking);
    cudaEvent_t evSetup, evX[SEQL];
    cudaEventCreateWithFlags(&evSetup, cudaEventDisableTiming);
    for (int t = 0; t < SEQL; t++)
        cudaEventCreateWithFlags(&evX[t], cudaEventDisableTiming);

    cudaEventRecord(evSetup, 0);
    cudaStreamWaitEvent(s1, evSetup, 0);
    for (int t = 0; t < SEQL; t++) {
        const __half* Xt = pXh + (size_t)t * SL;
        k_spmmT1<<<NB_SPMM, 256, 0, s1>>>(Xt, pT1X);
        k_fgemm<192, 0><<<NB_GEMM, 384, SM192, s1>>>(
            Xt, pT1X, pBX, pbX, nullptr, nullptr, nullptr,
            pGX + (size_t)t * SLK, nullptr, NN);
        cudaEventRecord(evX[t], s1);
    }

    // main-stream H chain
    cudaStreamWaitEvent(0, evX[0], 0);
    k_t0<<<(NN * CH + 255) / 256, 256>>>(pGX, b_hz, b_hh, out);

    for (int t = 1; t < SEQL; t++) {
        const float* Hp  = out + (size_t)(t - 1) * SL;
        const float* GXt = pGX + (size_t)t * SLK;
        float* Ot = out + (size_t)t * SL;

        k_spmmT1<<<NB_SPMM, 256>>>(pHh, pT1H);
        cudaStreamWaitEvent(0, evX[t], 0);
        k_fgemm<128, 1><<<NB_GEMM, 256, SM128>>>(
            pHh, pT1H, pBZR, pbZR, GXt, Hp, nullptr, pZ, pHRh, NN);
        k_spmmT1<<<NB_SPMM, 256>>>(pHRh, pT1H);
        k_fgemm<64, 2><<<NB_GEMM, 128, SM64>>>(
            pHRh, pT1H, pBH, b_hh, GXt, Hp, pZ, Ot, pHh, NN);
    }

    // Hlast = States[:, -1]
    if (out_size >= (int)((SEQL + 1) * SL)) {
        int n = (int)SL;
        k_copy<<<(n + 255) / 256, 256>>>(out + (size_t)(SEQL - 1) * SL,
                                         out + (size_t)SEQL * SL, n);
    }
}